// round 2
// baseline (speedup 1.0000x reference)
#include <cuda_runtime.h>
#include <cstdint>

#define N_NODES_MAX 100000
#define IN_FEATS    256
#define OUT_FEATS   64

// Scratch for h = x @ W  (25.6 MB) — __device__ global, no allocation.
__device__ float g_h[(size_t)N_NODES_MAX * OUT_FEATS];

// ---------------------------------------------------------------------------
// GEMM: h[n, 64] = x[n, 256] @ W[256, 64]   (fp32, smem-tiled, 8x8 reg tiles)
// Block tile: 128 rows x 64 cols, 128 threads, BK=32.
// ---------------------------------------------------------------------------
#define BM 128
#define BK 32

__global__ __launch_bounds__(128) void gemm_kernel(
    const float* __restrict__ x, const float* __restrict__ w,
    float* __restrict__ h, int n_rows)
{
    __shared__ float xs[BM][BK + 1];      // +1 pad vs bank conflicts
    __shared__ float ws[BK][OUT_FEATS];

    const int tid  = threadIdx.x;
    const int row0 = blockIdx.x * BM;
    const int ty   = tid >> 3;   // 0..15  (8 rows each)
    const int tx   = tid & 7;    // 0..7   (8 cols each)

    float acc[8][8];
#pragma unroll
    for (int i = 0; i < 8; i++)
#pragma unroll
        for (int j = 0; j < 8; j++) acc[i][j] = 0.f;

    for (int kk = 0; kk < IN_FEATS; kk += BK) {
        // Load x tile: 128 rows x 32 k = 1024 float4, 8 per thread, coalesced.
#pragma unroll
        for (int it = 0; it < 8; it++) {
            int idx = it * 128 + tid;
            int r   = idx >> 3;       // row within tile
            int kq  = idx & 7;        // which float4 in the 32-wide k-chunk
            int row = row0 + r;
            float4 v = make_float4(0.f, 0.f, 0.f, 0.f);
            if (row < n_rows)
                v = *(const float4*)&x[(size_t)row * IN_FEATS + kk + kq * 4];
            xs[r][kq * 4 + 0] = v.x; xs[r][kq * 4 + 1] = v.y;
            xs[r][kq * 4 + 2] = v.z; xs[r][kq * 4 + 3] = v.w;
        }
        // Load W tile: 32 k x 64 cols = 512 float4, 4 per thread.
#pragma unroll
        for (int it = 0; it < 4; it++) {
            int idx = it * 128 + tid;
            int kr  = idx >> 4;       // k row (0..31)
            int c4  = idx & 15;       // float4 col (0..15)
            *(float4*)&ws[kr][c4 * 4] =
                *(const float4*)&w[(size_t)(kk + kr) * OUT_FEATS + c4 * 4];
        }
        __syncthreads();

#pragma unroll
        for (int k = 0; k < BK; k++) {
            float a[8], b[8];
#pragma unroll
            for (int i = 0; i < 8; i++) a[i] = xs[ty * 8 + i][k];
#pragma unroll
            for (int j = 0; j < 8; j++) b[j] = ws[k][tx * 8 + j];
#pragma unroll
            for (int i = 0; i < 8; i++)
#pragma unroll
                for (int j = 0; j < 8; j++)
                    acc[i][j] = fmaf(a[i], b[j], acc[i][j]);
        }
        __syncthreads();
    }

#pragma unroll
    for (int i = 0; i < 8; i++) {
        int row = row0 + ty * 8 + i;
        if (row < n_rows) {
#pragma unroll
            for (int j = 0; j < 8; j += 4) {
                float4 v = make_float4(acc[i][j], acc[i][j + 1],
                                       acc[i][j + 2], acc[i][j + 3]);
                *(float4*)&h[(size_t)row * OUT_FEATS + tx * 8 + j] = v;
            }
        }
    }
}

// ---------------------------------------------------------------------------
// Init output to broadcast bias (d_out is poisoned, must be initialized).
// One float4 per thread; 16 float4 per node row.
// ---------------------------------------------------------------------------
__global__ void init_bias_kernel(float* __restrict__ out,
                                 const float* __restrict__ bias, int n4)
{
    int i = blockIdx.x * blockDim.x + threadIdx.x;
    if (i >= n4) return;
    int fb = (i & 15) * 4;                 // feature base within the 64-wide row
    ((float4*)out)[i] = *(const float4*)&bias[fb];
}

// ---------------------------------------------------------------------------
// Edge scatter: out[dst] += h[src] * ew, via red.global.add.v4.f32.
// 16 lanes per edge, one float4 (4 feats) per lane. Warp handles 2 edges.
// Indices are int32 (JAX x64-disabled downcasts int64 -> int32).
// ---------------------------------------------------------------------------
__global__ void edge_kernel(const float* __restrict__ h,
                            const int* __restrict__ src,
                            const int* __restrict__ dst,
                            const float* __restrict__ ew,
                            float* __restrict__ out, int n_edges)
{
    const int lane = threadIdx.x & 31;
    const long long warp =
        ((long long)blockIdx.x * blockDim.x + threadIdx.x) >> 5;
    const long long e = warp * 2 + (lane >> 4);
    if (e >= n_edges) return;
    const int sub = lane & 15;

    const int   s = src[e];
    const int   d = dst[e];
    const float wgt = ew[e];

    float4 v = *(const float4*)&h[(size_t)s * OUT_FEATS + sub * 4];
    v.x *= wgt; v.y *= wgt; v.z *= wgt; v.w *= wgt;

    float* p = &out[(size_t)d * OUT_FEATS + sub * 4];
    asm volatile("red.global.add.v4.f32 [%0], {%1, %2, %3, %4};"
                 :: "l"(p), "f"(v.x), "f"(v.y), "f"(v.z), "f"(v.w)
                 : "memory");
}

// ---------------------------------------------------------------------------
// ReLU in place.
// ---------------------------------------------------------------------------
__global__ void relu_kernel(float* __restrict__ out, int n4)
{
    int i = blockIdx.x * blockDim.x + threadIdx.x;
    if (i >= n4) return;
    float4 v = ((float4*)out)[i];
    v.x = fmaxf(v.x, 0.f); v.y = fmaxf(v.y, 0.f);
    v.z = fmaxf(v.z, 0.f); v.w = fmaxf(v.w, 0.f);
    ((float4*)out)[i] = v;
}

// ---------------------------------------------------------------------------
// Launch
// ---------------------------------------------------------------------------
extern "C" void kernel_launch(void* const* d_in, const int* in_sizes, int n_in,
                              void* d_out, int out_size)
{
    const float* x    = (const float*)d_in[0];
    const int*   src  = (const int*)d_in[1];
    const int*   dst  = (const int*)d_in[2];
    const float* ew   = (const float*)d_in[3];
    const float* w    = (const float*)d_in[4];
    const float* bias = (const float*)d_in[5];
    float*       out  = (float*)d_out;

    const int n_nodes = in_sizes[0] / IN_FEATS;
    const int n_edges = in_sizes[1];

    float* h = nullptr;
    cudaGetSymbolAddress((void**)&h, g_h);   // host query, not a stream op

    // 1) h = x @ W
    {
        int blocks = (n_nodes + BM - 1) / BM;
        gemm_kernel<<<blocks, 128>>>(x, w, h, n_nodes);
    }
    // 2) out = bias (broadcast)
    const int n4 = n_nodes * OUT_FEATS / 4;
    {
        int blocks = (n4 + 255) / 256;
        init_bias_kernel<<<blocks, 256>>>(out, bias, n4);
    }
    // 3) out[dst] += h[src] * ew  (vector L2 reductions)
    {
        long long threads_needed = (long long)n_edges * 16;
        int blocks = (int)((threads_needed + 255) / 256);
        edge_kernel<<<blocks, 256>>>(h, src, dst, ew, out, n_edges);
    }
    // 4) relu in place
    {
        int blocks = (n4 + 255) / 256;
        relu_kernel<<<blocks, 256>>>(out, n4);
    }
}

// round 3
// speedup vs baseline: 1.0519x; 1.0519x over previous
#include <cuda_runtime.h>
#include <cstdint>

#define N_NODES_MAX 100000
#define IN_FEATS    256
#define OUT_FEATS   64

__device__ float g_h[(size_t)N_NODES_MAX * OUT_FEATS];

// ---------------------------------------------------------------------------
// tf32 helpers
// ---------------------------------------------------------------------------
__device__ __forceinline__ unsigned f2tf32(float f) {
    unsigned r;
    asm("cvt.rna.tf32.f32 %0, %1;" : "=r"(r) : "f"(f));
    return r;
}

#define MMA_TF32(d, a, b)                                                     \
    asm volatile(                                                             \
        "mma.sync.aligned.m16n8k8.row.col.f32.tf32.tf32.f32 "                 \
        "{%0,%1,%2,%3}, {%4,%5,%6,%7}, {%8,%9}, {%0,%1,%2,%3};"               \
        : "+f"(d[0]), "+f"(d[1]), "+f"(d[2]), "+f"(d[3])                      \
        : "r"(a[0]), "r"(a[1]), "r"(a[2]), "r"(a[3]), "r"(b[0]), "r"(b[1]))

// ---------------------------------------------------------------------------
// GEMM: h[n,64] = x[n,256] @ W[256,64]  via 3xTF32 mma.sync (fp32 accuracy).
// Block: 128 M x 64 N, 256 threads = 8 warps (4x2), warp tile 32x32.
// ---------------------------------------------------------------------------
#define BM 128
#define BK 32
#define XS_PITCH 36   // bank = (4m + k) % 32 -> conflict-free A frags
#define WS_PITCH 72   // bank = (8k + n) % 32 -> conflict-free B frags

__global__ __launch_bounds__(256) void gemm_tf32_kernel(
    const float* __restrict__ x, const float* __restrict__ w,
    float* __restrict__ h, int n_rows)
{
    __shared__ float xs[BM][XS_PITCH];
    __shared__ float ws[BK][WS_PITCH];

    const int tid    = threadIdx.x;
    const int lane   = tid & 31;
    const int wid    = tid >> 5;
    const int warp_m = wid >> 1;       // 0..3 -> 32-row slab
    const int warp_n = wid & 1;        // 0..1 -> 32-col slab
    const int lq     = lane >> 2;      // 0..7
    const int lr     = lane & 3;       // 0..3
    const int row0   = blockIdx.x * BM;

    float acc[2][4][4];
#pragma unroll
    for (int mt = 0; mt < 2; mt++)
#pragma unroll
        for (int nt = 0; nt < 4; nt++)
#pragma unroll
            for (int r = 0; r < 4; r++) acc[mt][nt][r] = 0.f;

    for (int kk = 0; kk < IN_FEATS; kk += BK) {
        // load x tile: 128 rows x 32 k = 1024 float4, 4 per thread, coalesced
#pragma unroll
        for (int it = 0; it < 4; it++) {
            int idx = it * 256 + tid;
            int r   = idx >> 3;
            int kq  = idx & 7;
            float4 v = make_float4(0.f, 0.f, 0.f, 0.f);
            int row = row0 + r;
            if (row < n_rows)
                v = *(const float4*)&x[(size_t)row * IN_FEATS + kk + kq * 4];
            xs[r][kq * 4 + 0] = v.x; xs[r][kq * 4 + 1] = v.y;
            xs[r][kq * 4 + 2] = v.z; xs[r][kq * 4 + 3] = v.w;
        }
        // load W chunk: 32 k x 64 n = 512 float4, 2 per thread
#pragma unroll
        for (int it = 0; it < 2; it++) {
            int idx = it * 256 + tid;
            int kr  = idx >> 4;
            int c4  = idx & 15;
            float4 v = *(const float4*)&w[(size_t)(kk + kr) * OUT_FEATS + c4 * 4];
            ws[kr][c4 * 4 + 0] = v.x; ws[kr][c4 * 4 + 1] = v.y;
            ws[kr][c4 * 4 + 2] = v.z; ws[kr][c4 * 4 + 3] = v.w;
        }
        __syncthreads();

#pragma unroll
        for (int ks = 0; ks < 4; ks++) {
            const int kb = ks * 8;
            // A fragments (f32), then split hi/lo tf32
            float af[2][4];
#pragma unroll
            for (int mt = 0; mt < 2; mt++) {
                int mrow = warp_m * 32 + mt * 16;
                af[mt][0] = xs[mrow + lq    ][kb + lr    ];
                af[mt][1] = xs[mrow + lq + 8][kb + lr    ];
                af[mt][2] = xs[mrow + lq    ][kb + lr + 4];
                af[mt][3] = xs[mrow + lq + 8][kb + lr + 4];
            }
            float bf[4][2];
#pragma unroll
            for (int nt = 0; nt < 4; nt++) {
                int ncol = warp_n * 32 + nt * 8 + lq;
                bf[nt][0] = ws[kb + lr    ][ncol];
                bf[nt][1] = ws[kb + lr + 4][ncol];
            }

            unsigned ahi[2][4], alo[2][4], bhi[4][2], blo[4][2];
#pragma unroll
            for (int mt = 0; mt < 2; mt++)
#pragma unroll
                for (int r = 0; r < 4; r++) {
                    unsigned hi = f2tf32(af[mt][r]);
                    ahi[mt][r]  = hi;
                    alo[mt][r]  = f2tf32(af[mt][r] - __uint_as_float(hi));
                }
#pragma unroll
            for (int nt = 0; nt < 4; nt++)
#pragma unroll
                for (int r = 0; r < 2; r++) {
                    unsigned hi = f2tf32(bf[nt][r]);
                    bhi[nt][r]  = hi;
                    blo[nt][r]  = f2tf32(bf[nt][r] - __uint_as_float(hi));
                }

#pragma unroll
            for (int mt = 0; mt < 2; mt++)
#pragma unroll
                for (int nt = 0; nt < 4; nt++) {
                    MMA_TF32(acc[mt][nt], ahi[mt], bhi[nt]);
                    MMA_TF32(acc[mt][nt], ahi[mt], blo[nt]);
                    MMA_TF32(acc[mt][nt], alo[mt], bhi[nt]);
                }
        }
        __syncthreads();
    }

    // epilogue: c0/c1 -> (row, 2lr), (row, 2lr+1); c2/c3 -> row+8
#pragma unroll
    for (int mt = 0; mt < 2; mt++) {
        int rbase = row0 + warp_m * 32 + mt * 16 + lq;
#pragma unroll
        for (int nt = 0; nt < 4; nt++) {
            int col = warp_n * 32 + nt * 8 + 2 * lr;
            if (rbase < n_rows) {
                float2 v0 = make_float2(acc[mt][nt][0], acc[mt][nt][1]);
                *(float2*)&h[(size_t)rbase * OUT_FEATS + col] = v0;
            }
            if (rbase + 8 < n_rows) {
                float2 v1 = make_float2(acc[mt][nt][2], acc[mt][nt][3]);
                *(float2*)&h[(size_t)(rbase + 8) * OUT_FEATS + col] = v1;
            }
        }
    }
}

// ---------------------------------------------------------------------------
// Init output to broadcast bias.
// ---------------------------------------------------------------------------
__global__ void init_bias_kernel(float* __restrict__ out,
                                 const float* __restrict__ bias, int n4)
{
    int i = blockIdx.x * blockDim.x + threadIdx.x;
    if (i >= n4) return;
    int fb = (i & 15) * 4;
    ((float4*)out)[i] = *(const float4*)&bias[fb];
}

// ---------------------------------------------------------------------------
// Edge scatter: out[dst] += h[src] * ew via red.global.add.v4.f32.
// 16 lanes per edge, one float4 per lane.
// ---------------------------------------------------------------------------
__global__ void edge_kernel(const float* __restrict__ h,
                            const int* __restrict__ src,
                            const int* __restrict__ dst,
                            const float* __restrict__ ew,
                            float* __restrict__ out, int n_edges)
{
    const int lane = threadIdx.x & 31;
    const long long warp =
        ((long long)blockIdx.x * blockDim.x + threadIdx.x) >> 5;
    const long long e = warp * 2 + (lane >> 4);
    if (e >= n_edges) return;
    const int sub = lane & 15;

    const int   s   = src[e];
    const int   d   = dst[e];
    const float wgt = ew[e];

    float4 v = *(const float4*)&h[(size_t)s * OUT_FEATS + sub * 4];
    v.x *= wgt; v.y *= wgt; v.z *= wgt; v.w *= wgt;

    float* p = &out[(size_t)d * OUT_FEATS + sub * 4];
    asm volatile("red.global.add.v4.f32 [%0], {%1, %2, %3, %4};"
                 :: "l"(p), "f"(v.x), "f"(v.y), "f"(v.z), "f"(v.w)
                 : "memory");
}

// ---------------------------------------------------------------------------
// ReLU in place.
// ---------------------------------------------------------------------------
__global__ void relu_kernel(float* __restrict__ out, int n4)
{
    int i = blockIdx.x * blockDim.x + threadIdx.x;
    if (i >= n4) return;
    float4 v = ((float4*)out)[i];
    v.x = fmaxf(v.x, 0.f); v.y = fmaxf(v.y, 0.f);
    v.z = fmaxf(v.z, 0.f); v.w = fmaxf(v.w, 0.f);
    ((float4*)out)[i] = v;
}

// ---------------------------------------------------------------------------
// Launch
// ---------------------------------------------------------------------------
extern "C" void kernel_launch(void* const* d_in, const int* in_sizes, int n_in,
                              void* d_out, int out_size)
{
    const float* x    = (const float*)d_in[0];
    const int*   src  = (const int*)d_in[1];
    const int*   dst  = (const int*)d_in[2];
    const float* ew   = (const float*)d_in[3];
    const float* w    = (const float*)d_in[4];
    const float* bias = (const float*)d_in[5];
    float*       out  = (float*)d_out;

    const int n_nodes = in_sizes[0] / IN_FEATS;
    const int n_edges = in_sizes[1];

    float* h = nullptr;
    cudaGetSymbolAddress((void**)&h, g_h);

    // 1) h = x @ W  (tensor cores, 3xTF32)
    {
        int blocks = (n_nodes + BM - 1) / BM;
        gemm_tf32_kernel<<<blocks, 256>>>(x, w, h, n_nodes);
    }
    // 2) out = bias broadcast
    const int n4 = n_nodes * OUT_FEATS / 4;
    {
        int blocks = (n4 + 255) / 256;
        init_bias_kernel<<<blocks, 256>>>(out, bias, n4);
    }
    // 3) out[dst] += h[src] * ew
    {
        long long threads_needed = (long long)n_edges * 16;
        int blocks = (int)((threads_needed + 255) / 256);
        edge_kernel<<<blocks, 256>>>(h, src, dst, ew, out, n_edges);
    }
    // 4) relu in place
    {
        int blocks = (n4 + 255) / 256;
        relu_kernel<<<blocks, 256>>>(out, n4);
    }
}

// round 4
// speedup vs baseline: 1.1252x; 1.0696x over previous
#include <cuda_runtime.h>
#include <cstdint>

#define N_NODES_MAX 100032
#define E_MAX       1600000
#define IN_FEATS    256
#define OUT_FEATS   64

// Scratch (all __device__ globals, no allocation):
__device__ float g_h[(size_t)N_NODES_MAX * OUT_FEATS];   // x @ W
__device__ int   g_count[N_NODES_MAX];
__device__ int   g_start[N_NODES_MAX];
__device__ int   g_cursor[N_NODES_MAX];
__device__ int   g_bsum[256];
__device__ int   g_bsrc[E_MAX];
__device__ float g_bw[E_MAX];

// ---------------------------------------------------------------------------
// tf32 helpers
// ---------------------------------------------------------------------------
__device__ __forceinline__ unsigned f2tf32(float f) {
    unsigned r;
    asm("cvt.rna.tf32.f32 %0, %1;" : "=r"(r) : "f"(f));
    return r;
}

#define MMA_TF32(d, a, b)                                                     \
    asm volatile(                                                             \
        "mma.sync.aligned.m16n8k8.row.col.f32.tf32.tf32.f32 "                 \
        "{%0,%1,%2,%3}, {%4,%5,%6,%7}, {%8,%9}, {%0,%1,%2,%3};"               \
        : "+f"(d[0]), "+f"(d[1]), "+f"(d[2]), "+f"(d[3])                      \
        : "r"(a[0]), "r"(a[1]), "r"(a[2]), "r"(a[3]), "r"(b[0]), "r"(b[1]))

// ---------------------------------------------------------------------------
// GEMM: h[n,64] = x[n,256] @ W[256,64] via 3xTF32 mma.sync.
// ---------------------------------------------------------------------------
#define BM 128
#define BK 32
#define XS_PITCH 36
#define WS_PITCH 72

__global__ __launch_bounds__(256) void gemm_tf32_kernel(
    const float* __restrict__ x, const float* __restrict__ w,
    float* __restrict__ h, int n_rows)
{
    __shared__ float xs[BM][XS_PITCH];
    __shared__ float ws[BK][WS_PITCH];

    const int tid    = threadIdx.x;
    const int lane   = tid & 31;
    const int wid    = tid >> 5;
    const int warp_m = wid >> 1;
    const int warp_n = wid & 1;
    const int lq     = lane >> 2;
    const int lr     = lane & 3;
    const int row0   = blockIdx.x * BM;

    float acc[2][4][4];
#pragma unroll
    for (int mt = 0; mt < 2; mt++)
#pragma unroll
        for (int nt = 0; nt < 4; nt++)
#pragma unroll
            for (int r = 0; r < 4; r++) acc[mt][nt][r] = 0.f;

    for (int kk = 0; kk < IN_FEATS; kk += BK) {
#pragma unroll
        for (int it = 0; it < 4; it++) {
            int idx = it * 256 + tid;
            int r   = idx >> 3;
            int kq  = idx & 7;
            float4 v = make_float4(0.f, 0.f, 0.f, 0.f);
            int row = row0 + r;
            if (row < n_rows)
                v = *(const float4*)&x[(size_t)row * IN_FEATS + kk + kq * 4];
            xs[r][kq * 4 + 0] = v.x; xs[r][kq * 4 + 1] = v.y;
            xs[r][kq * 4 + 2] = v.z; xs[r][kq * 4 + 3] = v.w;
        }
#pragma unroll
        for (int it = 0; it < 2; it++) {
            int idx = it * 256 + tid;
            int kr  = idx >> 4;
            int c4  = idx & 15;
            float4 v = *(const float4*)&w[(size_t)(kk + kr) * OUT_FEATS + c4 * 4];
            ws[kr][c4 * 4 + 0] = v.x; ws[kr][c4 * 4 + 1] = v.y;
            ws[kr][c4 * 4 + 2] = v.z; ws[kr][c4 * 4 + 3] = v.w;
        }
        __syncthreads();

#pragma unroll
        for (int ks = 0; ks < 4; ks++) {
            const int kb = ks * 8;
            float af[2][4];
#pragma unroll
            for (int mt = 0; mt < 2; mt++) {
                int mrow = warp_m * 32 + mt * 16;
                af[mt][0] = xs[mrow + lq    ][kb + lr    ];
                af[mt][1] = xs[mrow + lq + 8][kb + lr    ];
                af[mt][2] = xs[mrow + lq    ][kb + lr + 4];
                af[mt][3] = xs[mrow + lq + 8][kb + lr + 4];
            }
            float bf[4][2];
#pragma unroll
            for (int nt = 0; nt < 4; nt++) {
                int ncol = warp_n * 32 + nt * 8 + lq;
                bf[nt][0] = ws[kb + lr    ][ncol];
                bf[nt][1] = ws[kb + lr + 4][ncol];
            }

            unsigned ahi[2][4], alo[2][4], bhi[4][2], blo[4][2];
#pragma unroll
            for (int mt = 0; mt < 2; mt++)
#pragma unroll
                for (int r = 0; r < 4; r++) {
                    unsigned hi = f2tf32(af[mt][r]);
                    ahi[mt][r]  = hi;
                    alo[mt][r]  = f2tf32(af[mt][r] - __uint_as_float(hi));
                }
#pragma unroll
            for (int nt = 0; nt < 4; nt++)
#pragma unroll
                for (int r = 0; r < 2; r++) {
                    unsigned hi = f2tf32(bf[nt][r]);
                    bhi[nt][r]  = hi;
                    blo[nt][r]  = f2tf32(bf[nt][r] - __uint_as_float(hi));
                }

#pragma unroll
            for (int mt = 0; mt < 2; mt++)
#pragma unroll
                for (int nt = 0; nt < 4; nt++) {
                    MMA_TF32(acc[mt][nt], ahi[mt], bhi[nt]);
                    MMA_TF32(acc[mt][nt], ahi[mt], blo[nt]);
                    MMA_TF32(acc[mt][nt], alo[mt], bhi[nt]);
                }
        }
        __syncthreads();
    }

#pragma unroll
    for (int mt = 0; mt < 2; mt++) {
        int rbase = row0 + warp_m * 32 + mt * 16 + lq;
#pragma unroll
        for (int nt = 0; nt < 4; nt++) {
            int col = warp_n * 32 + nt * 8 + 2 * lr;
            if (rbase < n_rows) {
                float2 v0 = make_float2(acc[mt][nt][0], acc[mt][nt][1]);
                *(float2*)&h[(size_t)rbase * OUT_FEATS + col] = v0;
            }
            if (rbase + 8 < n_rows) {
                float2 v1 = make_float2(acc[mt][nt][2], acc[mt][nt][3]);
                *(float2*)&h[(size_t)(rbase + 8) * OUT_FEATS + col] = v1;
            }
        }
    }
}

// ---------------------------------------------------------------------------
// CSR build
// ---------------------------------------------------------------------------
__global__ void zero_counts_kernel(int* __restrict__ count, int n)
{
    int i = blockIdx.x * blockDim.x + threadIdx.x;
    if (i < n) count[i] = 0;
}

__global__ void hist_kernel(const int* __restrict__ dst,
                            int* __restrict__ count, int n_edges)
{
    int i = blockIdx.x * blockDim.x + threadIdx.x;
    if (i < n_edges) atomicAdd(&count[dst[i]], 1);
}

// scan within 1024-element blocks -> exclusive, block totals to bsum
__global__ __launch_bounds__(1024) void scan1_kernel(
    const int* __restrict__ count, int* __restrict__ start,
    int* __restrict__ bsum, int n)
{
    __shared__ int sm[1024];
    int tid = threadIdx.x;
    int gid = blockIdx.x * 1024 + tid;
    int v = (gid < n) ? count[gid] : 0;
    sm[tid] = v;
    __syncthreads();
#pragma unroll
    for (int off = 1; off < 1024; off <<= 1) {
        int t = (tid >= off) ? sm[tid - off] : 0;
        __syncthreads();
        sm[tid] += t;
        __syncthreads();
    }
    if (gid < n) start[gid] = sm[tid] - v;     // exclusive
    if (tid == 1023) bsum[blockIdx.x] = sm[1023];
}

__global__ void scan2_kernel(int* __restrict__ bsum, int nb)
{
    if (threadIdx.x == 0) {
        int running = 0;
        for (int b = 0; b < nb; b++) {
            int t = bsum[b];
            bsum[b] = running;
            running += t;
        }
    }
}

__global__ void scan3_kernel(int* __restrict__ start,
                             int* __restrict__ cursor,
                             const int* __restrict__ bsum, int n)
{
    int i = blockIdx.x * blockDim.x + threadIdx.x;
    if (i < n) {
        int s = start[i] + bsum[i >> 10];
        start[i]  = s;
        cursor[i] = s;
    }
}

__global__ void scatter_kernel(const int* __restrict__ src,
                               const int* __restrict__ dst,
                               const float* __restrict__ ew,
                               int* __restrict__ cursor,
                               int* __restrict__ bsrc,
                               float* __restrict__ bw, int n_edges)
{
    int i = blockIdx.x * blockDim.x + threadIdx.x;
    if (i >= n_edges) return;
    int d = dst[i];
    int pos = atomicAdd(&cursor[d], 1);
    bsrc[pos] = src[i];
    bw[pos]   = ew[i];
}

// ---------------------------------------------------------------------------
// Aggregate: one warp per node; lane owns 2 feats (float2 accumulator).
// out[n] = relu(sum_{e in bucket(n)} h[bsrc[e]] * bw[e] + bias)
// ---------------------------------------------------------------------------
__global__ __launch_bounds__(256) void aggregate_kernel(
    const float* __restrict__ h,
    const int* __restrict__ start,
    const int* __restrict__ bsrc,
    const float* __restrict__ bw,
    const float* __restrict__ bias,
    float* __restrict__ out, int n_nodes, int n_edges)
{
    const int lane = threadIdx.x & 31;
    const int node = (blockIdx.x * blockDim.x + threadIdx.x) >> 5;
    if (node >= n_nodes) return;

    const int beg = start[node];
    const int end = (node + 1 < n_nodes) ? start[node + 1] : n_edges;

    float2 acc = make_float2(0.f, 0.f);

    for (int j = beg; j < end; j += 32) {
        int idx = j + lane;
        int s   = 0;
        float wv = 0.f;
        if (idx < end) { s = bsrc[idx]; wv = bw[idx]; }
        int cnt = min(32, end - j);
#pragma unroll 4
        for (int i = 0; i < cnt; i++) {
            int   si = __shfl_sync(0xffffffffu, s,  i);
            float wi = __shfl_sync(0xffffffffu, wv, i);
            float2 hv = *(const float2*)&h[(size_t)si * OUT_FEATS + lane * 2];
            acc.x = fmaf(hv.x, wi, acc.x);
            acc.y = fmaf(hv.y, wi, acc.y);
        }
    }

    float2 bv = *(const float2*)&bias[lane * 2];
    acc.x = fmaxf(acc.x + bv.x, 0.f);
    acc.y = fmaxf(acc.y + bv.y, 0.f);
    *(float2*)&out[(size_t)node * OUT_FEATS + lane * 2] = acc;
}

// ---------------------------------------------------------------------------
// Launch
// ---------------------------------------------------------------------------
extern "C" void kernel_launch(void* const* d_in, const int* in_sizes, int n_in,
                              void* d_out, int out_size)
{
    const float* x    = (const float*)d_in[0];
    const int*   src  = (const int*)d_in[1];
    const int*   dst  = (const int*)d_in[2];
    const float* ew   = (const float*)d_in[3];
    const float* w    = (const float*)d_in[4];
    const float* bias = (const float*)d_in[5];
    float*       out  = (float*)d_out;

    const int n_nodes = in_sizes[0] / IN_FEATS;
    const int n_edges = in_sizes[1];

    float* h;      cudaGetSymbolAddress((void**)&h,      g_h);
    int*   count;  cudaGetSymbolAddress((void**)&count,  g_count);
    int*   start;  cudaGetSymbolAddress((void**)&start,  g_start);
    int*   cursor; cudaGetSymbolAddress((void**)&cursor, g_cursor);
    int*   bsum;   cudaGetSymbolAddress((void**)&bsum,   g_bsum);
    int*   bsrc;   cudaGetSymbolAddress((void**)&bsrc,   g_bsrc);
    float* bw;     cudaGetSymbolAddress((void**)&bw,     g_bw);

    // 1) h = x @ W  (tensor cores, 3xTF32)
    gemm_tf32_kernel<<<(n_nodes + BM - 1) / BM, 256>>>(x, w, h, n_nodes);

    // 2) reverse-CSR build
    zero_counts_kernel<<<(n_nodes + 255) / 256, 256>>>(count, n_nodes);
    hist_kernel<<<(n_edges + 255) / 256, 256>>>(dst, count, n_edges);
    const int nb = (n_nodes + 1023) / 1024;
    scan1_kernel<<<nb, 1024>>>(count, start, bsum, n_nodes);
    scan2_kernel<<<1, 32>>>(bsum, nb);
    scan3_kernel<<<(n_nodes + 255) / 256, 256>>>(start, cursor, bsum, n_nodes);
    scatter_kernel<<<(n_edges + 255) / 256, 256>>>(src, dst, ew, cursor,
                                                   bsrc, bw, n_edges);

    // 3) aggregate + bias + relu (one warp per node, no atomics)
    {
        long long threads = (long long)n_nodes * 32;
        int blocks = (int)((threads + 255) / 256);
        aggregate_kernel<<<blocks, 256>>>(h, start, bsrc, bw, bias,
                                          out, n_nodes, n_edges);
    }
}

// round 5
// speedup vs baseline: 1.2050x; 1.0710x over previous
#include <cuda_runtime.h>
#include <cstdint>

#define N_NODES_MAX 100032
#define E_MAX       1600000
#define IN_FEATS    256
#define OUT_FEATS   64

// Scratch (all __device__ globals, no allocation):
__device__ float g_h[(size_t)N_NODES_MAX * OUT_FEATS];   // x @ W
__device__ int   g_count[N_NODES_MAX];
__device__ int   g_start[N_NODES_MAX];
__device__ int   g_cursor[N_NODES_MAX];
__device__ int   g_total;
__device__ int2  g_edge[E_MAX];                          // {src, w_bits}

// ---------------------------------------------------------------------------
// tf32 helpers
// ---------------------------------------------------------------------------
__device__ __forceinline__ unsigned f2tf32(float f) {
    unsigned r;
    asm("cvt.rna.tf32.f32 %0, %1;" : "=r"(r) : "f"(f));
    return r;
}

#define MMA_TF32(d, a, b)                                                     \
    asm volatile(                                                             \
        "mma.sync.aligned.m16n8k8.row.col.f32.tf32.tf32.f32 "                 \
        "{%0,%1,%2,%3}, {%4,%5,%6,%7}, {%8,%9}, {%0,%1,%2,%3};"               \
        : "+f"(d[0]), "+f"(d[1]), "+f"(d[2]), "+f"(d[3])                      \
        : "r"(a[0]), "r"(a[1]), "r"(a[2]), "r"(a[3]), "r"(b[0]), "r"(b[1]))

// ---------------------------------------------------------------------------
// GEMM: h[n,64] = x[n,256] @ W[256,64] via 3xTF32 mma.sync.
// ---------------------------------------------------------------------------
#define BM 128
#define BK 32
#define XS_PITCH 36
#define WS_PITCH 72

__global__ __launch_bounds__(256) void gemm_tf32_kernel(
    const float* __restrict__ x, const float* __restrict__ w,
    float* __restrict__ h, int n_rows)
{
    __shared__ float xs[BM][XS_PITCH];
    __shared__ float ws[BK][WS_PITCH];

    const int tid    = threadIdx.x;
    const int lane   = tid & 31;
    const int wid    = tid >> 5;
    const int warp_m = wid >> 1;
    const int warp_n = wid & 1;
    const int lq     = lane >> 2;
    const int lr     = lane & 3;
    const int row0   = blockIdx.x * BM;

    float acc[2][4][4];
#pragma unroll
    for (int mt = 0; mt < 2; mt++)
#pragma unroll
        for (int nt = 0; nt < 4; nt++)
#pragma unroll
            for (int r = 0; r < 4; r++) acc[mt][nt][r] = 0.f;

    for (int kk = 0; kk < IN_FEATS; kk += BK) {
#pragma unroll
        for (int it = 0; it < 4; it++) {
            int idx = it * 256 + tid;
            int r   = idx >> 3;
            int kq  = idx & 7;
            float4 v = make_float4(0.f, 0.f, 0.f, 0.f);
            int row = row0 + r;
            if (row < n_rows)
                v = *(const float4*)&x[(size_t)row * IN_FEATS + kk + kq * 4];
            xs[r][kq * 4 + 0] = v.x; xs[r][kq * 4 + 1] = v.y;
            xs[r][kq * 4 + 2] = v.z; xs[r][kq * 4 + 3] = v.w;
        }
#pragma unroll
        for (int it = 0; it < 2; it++) {
            int idx = it * 256 + tid;
            int kr  = idx >> 4;
            int c4  = idx & 15;
            float4 v = *(const float4*)&w[(size_t)(kk + kr) * OUT_FEATS + c4 * 4];
            ws[kr][c4 * 4 + 0] = v.x; ws[kr][c4 * 4 + 1] = v.y;
            ws[kr][c4 * 4 + 2] = v.z; ws[kr][c4 * 4 + 3] = v.w;
        }
        __syncthreads();

#pragma unroll
        for (int ks = 0; ks < 4; ks++) {
            const int kb = ks * 8;
            float af[2][4];
#pragma unroll
            for (int mt = 0; mt < 2; mt++) {
                int mrow = warp_m * 32 + mt * 16;
                af[mt][0] = xs[mrow + lq    ][kb + lr    ];
                af[mt][1] = xs[mrow + lq + 8][kb + lr    ];
                af[mt][2] = xs[mrow + lq    ][kb + lr + 4];
                af[mt][3] = xs[mrow + lq + 8][kb + lr + 4];
            }
            float bf[4][2];
#pragma unroll
            for (int nt = 0; nt < 4; nt++) {
                int ncol = warp_n * 32 + nt * 8 + lq;
                bf[nt][0] = ws[kb + lr    ][ncol];
                bf[nt][1] = ws[kb + lr + 4][ncol];
            }

            unsigned ahi[2][4], alo[2][4], bhi[4][2], blo[4][2];
#pragma unroll
            for (int mt = 0; mt < 2; mt++)
#pragma unroll
                for (int r = 0; r < 4; r++) {
                    unsigned hi = f2tf32(af[mt][r]);
                    ahi[mt][r]  = hi;
                    alo[mt][r]  = f2tf32(af[mt][r] - __uint_as_float(hi));
                }
#pragma unroll
            for (int nt = 0; nt < 4; nt++)
#pragma unroll
                for (int r = 0; r < 2; r++) {
                    unsigned hi = f2tf32(bf[nt][r]);
                    bhi[nt][r]  = hi;
                    blo[nt][r]  = f2tf32(bf[nt][r] - __uint_as_float(hi));
                }

#pragma unroll
            for (int mt = 0; mt < 2; mt++)
#pragma unroll
                for (int nt = 0; nt < 4; nt++) {
                    MMA_TF32(acc[mt][nt], ahi[mt], bhi[nt]);
                    MMA_TF32(acc[mt][nt], ahi[mt], blo[nt]);
                    MMA_TF32(acc[mt][nt], alo[mt], bhi[nt]);
                }
        }
        __syncthreads();
    }

#pragma unroll
    for (int mt = 0; mt < 2; mt++) {
        int rbase = row0 + warp_m * 32 + mt * 16 + lq;
#pragma unroll
        for (int nt = 0; nt < 4; nt++) {
            int col = warp_n * 32 + nt * 8 + 2 * lr;
            if (rbase < n_rows) {
                float2 v0 = make_float2(acc[mt][nt][0], acc[mt][nt][1]);
                *(float2*)&h[(size_t)rbase * OUT_FEATS + col] = v0;
            }
            if (rbase + 8 < n_rows) {
                float2 v1 = make_float2(acc[mt][nt][2], acc[mt][nt][3]);
                *(float2*)&h[(size_t)(rbase + 8) * OUT_FEATS + col] = v1;
            }
        }
    }
}

// ---------------------------------------------------------------------------
// CSR build
// ---------------------------------------------------------------------------
__global__ void zero_counts_kernel(int* __restrict__ count,
                                   int* __restrict__ total, int n)
{
    int i = blockIdx.x * blockDim.x + threadIdx.x;
    if (i < n) count[i] = 0;
    if (i == 0) *total = 0;
}

__global__ void hist_kernel(const int* __restrict__ dst,
                            int* __restrict__ count, int n_edges)
{
    int i = blockIdx.x * blockDim.x + threadIdx.x;
    if (i < n_edges) atomicAdd(&count[dst[i]], 1);
}

// Block scan of counts + atomic base allocation (buckets contiguous but in
// arbitrary block order — aggregation only needs [start, start+count)).
__global__ __launch_bounds__(1024) void scanalloc_kernel(
    const int* __restrict__ count, int* __restrict__ start,
    int* __restrict__ cursor, int* __restrict__ total, int n)
{
    __shared__ int warp_sums[32];
    __shared__ int block_base;

    const int tid  = threadIdx.x;
    const int lane = tid & 31;
    const int wid  = tid >> 5;
    const int gid  = blockIdx.x * 1024 + tid;

    int v = (gid < n) ? count[gid] : 0;

    // warp inclusive scan
    int x = v;
#pragma unroll
    for (int off = 1; off < 32; off <<= 1) {
        int t = __shfl_up_sync(0xffffffffu, x, off);
        if (lane >= off) x += t;
    }
    if (lane == 31) warp_sums[wid] = x;
    __syncthreads();

    if (wid == 0) {
        int s = warp_sums[lane];
#pragma unroll
        for (int off = 1; off < 32; off <<= 1) {
            int t = __shfl_up_sync(0xffffffffu, s, off);
            if (lane >= off) s += t;
        }
        warp_sums[lane] = s;
        if (lane == 31) block_base = atomicAdd(total, s);  // s = block total
    }
    __syncthreads();

    int prefix = block_base + (wid > 0 ? warp_sums[wid - 1] : 0) + (x - v);
    if (gid < n) {
        start[gid]  = prefix;
        cursor[gid] = prefix;
    }
}

__global__ void scatter_kernel(const int* __restrict__ src,
                               const int* __restrict__ dst,
                               const float* __restrict__ ew,
                               int* __restrict__ cursor,
                               int2* __restrict__ edge, int n_edges)
{
    int i = blockIdx.x * blockDim.x + threadIdx.x;
    if (i >= n_edges) return;
    int d = dst[i];
    int pos = atomicAdd(&cursor[d], 1);
    edge[pos] = make_int2(src[i], __float_as_int(ew[i]));
}

// ---------------------------------------------------------------------------
// Aggregate: one warp per node; lane owns 2 feats.
// out[n] = relu(sum_{e in bucket(n)} h[src_e] * w_e + bias)
// ---------------------------------------------------------------------------
__global__ __launch_bounds__(256) void aggregate_kernel(
    const float* __restrict__ h,
    const int* __restrict__ start,
    const int* __restrict__ count,
    const int2* __restrict__ edge,
    const float* __restrict__ bias,
    float* __restrict__ out, int n_nodes)
{
    const int lane = threadIdx.x & 31;
    const int node = (blockIdx.x * blockDim.x + threadIdx.x) >> 5;
    if (node >= n_nodes) return;

    const int beg = start[node];
    const int end = beg + count[node];

    float2 acc = make_float2(0.f, 0.f);

    for (int j = beg; j < end; j += 32) {
        int idx = j + lane;
        int2 e = (idx < end) ? edge[idx] : make_int2(0, 0);  // w=0.0f pad
        int cnt = min(32, end - j);
#pragma unroll 8
        for (int i = 0; i < cnt; i++) {
            int   si = __shfl_sync(0xffffffffu, e.x, i);
            float wi = __int_as_float(__shfl_sync(0xffffffffu, e.y, i));
            float2 hv = *(const float2*)&h[(size_t)si * OUT_FEATS + lane * 2];
            acc.x = fmaf(hv.x, wi, acc.x);
            acc.y = fmaf(hv.y, wi, acc.y);
        }
    }

    float2 bv = *(const float2*)&bias[lane * 2];
    acc.x = fmaxf(acc.x + bv.x, 0.f);
    acc.y = fmaxf(acc.y + bv.y, 0.f);
    *(float2*)&out[(size_t)node * OUT_FEATS + lane * 2] = acc;
}

// ---------------------------------------------------------------------------
// Launch
// ---------------------------------------------------------------------------
extern "C" void kernel_launch(void* const* d_in, const int* in_sizes, int n_in,
                              void* d_out, int out_size)
{
    const float* x    = (const float*)d_in[0];
    const int*   src  = (const int*)d_in[1];
    const int*   dst  = (const int*)d_in[2];
    const float* ew   = (const float*)d_in[3];
    const float* w    = (const float*)d_in[4];
    const float* bias = (const float*)d_in[5];
    float*       out  = (float*)d_out;

    const int n_nodes = in_sizes[0] / IN_FEATS;
    const int n_edges = in_sizes[1];

    float* h;      cudaGetSymbolAddress((void**)&h,      g_h);
    int*   count;  cudaGetSymbolAddress((void**)&count,  g_count);
    int*   start;  cudaGetSymbolAddress((void**)&start,  g_start);
    int*   cursor; cudaGetSymbolAddress((void**)&cursor, g_cursor);
    int*   total;  cudaGetSymbolAddress((void**)&total,  g_total);
    int2*  edge;   cudaGetSymbolAddress((void**)&edge,   g_edge);

    // 1) h = x @ W  (tensor cores, 3xTF32)
    gemm_tf32_kernel<<<(n_nodes + BM - 1) / BM, 256>>>(x, w, h, n_nodes);

    // 2) reverse-CSR build (hist -> scan+alloc -> scatter)
    zero_counts_kernel<<<(n_nodes + 255) / 256, 256>>>(count, total, n_nodes);
    hist_kernel<<<(n_edges + 255) / 256, 256>>>(dst, count, n_edges);
    scanalloc_kernel<<<(n_nodes + 1023) / 1024, 1024>>>(count, start, cursor,
                                                        total, n_nodes);
    scatter_kernel<<<(n_edges + 255) / 256, 256>>>(src, dst, ew, cursor,
                                                   edge, n_edges);

    // 3) aggregate + bias + relu (one warp per node, no float atomics)
    {
        long long threads = (long long)n_nodes * 32;
        int blocks = (int)((threads + 255) / 256);
        aggregate_kernel<<<blocks, 256>>>(h, start, count, edge, bias,
                                          out, n_nodes);
    }
}

// round 6
// speedup vs baseline: 1.4288x; 1.1857x over previous
#include <cuda_runtime.h>
#include <cstdint>

#define N_NODES_MAX 100032
#define E_MAX       1600000
#define IN_FEATS    256
#define OUT_FEATS   64

// Scratch (all __device__ globals, no allocation):
__device__ float g_h[(size_t)N_NODES_MAX * OUT_FEATS];   // x @ W
__device__ int   g_count[N_NODES_MAX];
__device__ int   g_start[N_NODES_MAX];
__device__ int   g_cursor[N_NODES_MAX];
__device__ int   g_total;
__device__ int2  g_edge[E_MAX];                          // {src, w_bits}

// ---------------------------------------------------------------------------
// bf16 helpers: pack two floats to bf16x2 (x -> low, y -> high)
// ---------------------------------------------------------------------------
__device__ __forceinline__ unsigned pack_bf16x2(float lo, float hi) {
    unsigned r;
    asm("cvt.rn.bf16x2.f32 %0, %1, %2;" : "=r"(r) : "f"(hi), "f"(lo));
    return r;
}

// split float2 v into bf16x2 hi + bf16x2 lo (residual)
__device__ __forceinline__ void split_bf16(float2 v, unsigned& hi, unsigned& lo) {
    hi = pack_bf16x2(v.x, v.y);
    float rx = v.x - __uint_as_float(hi << 16);
    float ry = v.y - __uint_as_float(hi & 0xffff0000u);
    lo = pack_bf16x2(rx, ry);
}

#define MMA_BF16(d, a, b)                                                     \
    asm volatile(                                                             \
        "mma.sync.aligned.m16n8k16.row.col.f32.bf16.bf16.f32 "                \
        "{%0,%1,%2,%3}, {%4,%5,%6,%7}, {%8,%9}, {%0,%1,%2,%3};"               \
        : "+f"(d[0]), "+f"(d[1]), "+f"(d[2]), "+f"(d[3])                      \
        : "r"(a[0]), "r"(a[1]), "r"(a[2]), "r"(a[3]), "r"(b[0]), "r"(b[1]))

// ---------------------------------------------------------------------------
// GEMM: h[n,64] = x[n,256] @ W[256,64] via 3-term bf16 split on m16n8k16.
// Block: 128M x 64N, 256 threads = 8 warps (4x2), warp tile 32x32.
// Also zeroes the CSR counters (fused, independent data).
// ---------------------------------------------------------------------------
#define BM 128
#define BK 32
#define XS_PITCH 40   // LDS.64 conflict-free per half-warp
#define WS_PITCH 68   // scalar LDS conflict-free across full warp

__global__ __launch_bounds__(256) void gemm_bf16x_kernel(
    const float* __restrict__ x, const float* __restrict__ w,
    float* __restrict__ h, int n_rows,
    int* __restrict__ count, int* __restrict__ total, int n_nodes)
{
    // fused CSR-counter zeroing (runs before hist in stream order)
    {
        int gid = blockIdx.x * 256 + threadIdx.x;
        if (gid < n_nodes) count[gid] = 0;
        if (gid == 0) *total = 0;
    }

    __shared__ float xs[BM][XS_PITCH];
    __shared__ float ws[BK][WS_PITCH];

    const int tid    = threadIdx.x;
    const int lane   = tid & 31;
    const int wid    = tid >> 5;
    const int warp_m = wid >> 1;
    const int warp_n = wid & 1;
    const int lq     = lane >> 2;      // 0..7
    const int lr     = lane & 3;       // 0..3
    const int row0   = blockIdx.x * BM;

    float acc[2][4][4];
#pragma unroll
    for (int mt = 0; mt < 2; mt++)
#pragma unroll
        for (int nt = 0; nt < 4; nt++)
#pragma unroll
            for (int r = 0; r < 4; r++) acc[mt][nt][r] = 0.f;

    for (int kk = 0; kk < IN_FEATS; kk += BK) {
        // load x tile: 128 rows x 32 k, 4 float4 per thread, coalesced
#pragma unroll
        for (int it = 0; it < 4; it++) {
            int idx = it * 256 + tid;
            int r   = idx >> 3;
            int kq  = idx & 7;
            float4 v = make_float4(0.f, 0.f, 0.f, 0.f);
            int row = row0 + r;
            if (row < n_rows)
                v = *(const float4*)&x[(size_t)row * IN_FEATS + kk + kq * 4];
            *(float4*)&xs[r][kq * 4] = v;
        }
        // load W chunk: 32 k x 64 n, 2 float4 per thread
#pragma unroll
        for (int it = 0; it < 2; it++) {
            int idx = it * 256 + tid;
            int kr  = idx >> 4;
            int c4  = idx & 15;
            *(float4*)&ws[kr][c4 * 4] =
                *(const float4*)&w[(size_t)(kk + kr) * OUT_FEATS + c4 * 4];
        }
        __syncthreads();

#pragma unroll
        for (int ks = 0; ks < 2; ks++) {          // two k16 steps per tile
            const int kb = ks * 16;

            unsigned ahi[2][4], alo[2][4];
#pragma unroll
            for (int mt = 0; mt < 2; mt++) {
                int mrow = warp_m * 32 + mt * 16;
                float2 a0 = *(const float2*)&xs[mrow + lq    ][kb + 2 * lr    ];
                float2 a1 = *(const float2*)&xs[mrow + lq + 8][kb + 2 * lr    ];
                float2 a2 = *(const float2*)&xs[mrow + lq    ][kb + 2 * lr + 8];
                float2 a3 = *(const float2*)&xs[mrow + lq + 8][kb + 2 * lr + 8];
                split_bf16(a0, ahi[mt][0], alo[mt][0]);
                split_bf16(a1, ahi[mt][1], alo[mt][1]);
                split_bf16(a2, ahi[mt][2], alo[mt][2]);
                split_bf16(a3, ahi[mt][3], alo[mt][3]);
            }
            unsigned bhi[4][2], blo[4][2];
#pragma unroll
            for (int nt = 0; nt < 4; nt++) {
                int ncol = warp_n * 32 + nt * 8 + lq;
                float2 b0 = make_float2(ws[kb + 2 * lr    ][ncol],
                                        ws[kb + 2 * lr + 1][ncol]);
                float2 b1 = make_float2(ws[kb + 2 * lr + 8][ncol],
                                        ws[kb + 2 * lr + 9][ncol]);
                split_bf16(b0, bhi[nt][0], blo[nt][0]);
                split_bf16(b1, bhi[nt][1], blo[nt][1]);
            }

#pragma unroll
            for (int mt = 0; mt < 2; mt++)
#pragma unroll
                for (int nt = 0; nt < 4; nt++) {
                    MMA_BF16(acc[mt][nt], ahi[mt], bhi[nt]);
                    MMA_BF16(acc[mt][nt], ahi[mt], blo[nt]);
                    MMA_BF16(acc[mt][nt], alo[mt], bhi[nt]);
                }
        }
        __syncthreads();
    }

    // epilogue: c0/c1 -> (row, 2lr, 2lr+1); c2/c3 -> row+8
#pragma unroll
    for (int mt = 0; mt < 2; mt++) {
        int rbase = row0 + warp_m * 32 + mt * 16 + lq;
#pragma unroll
        for (int nt = 0; nt < 4; nt++) {
            int col = warp_n * 32 + nt * 8 + 2 * lr;
            if (rbase < n_rows) {
                float2 v0 = make_float2(acc[mt][nt][0], acc[mt][nt][1]);
                *(float2*)&h[(size_t)rbase * OUT_FEATS + col] = v0;
            }
            if (rbase + 8 < n_rows) {
                float2 v1 = make_float2(acc[mt][nt][2], acc[mt][nt][3]);
                *(float2*)&h[(size_t)(rbase + 8) * OUT_FEATS + col] = v1;
            }
        }
    }
}

// ---------------------------------------------------------------------------
// CSR build
// ---------------------------------------------------------------------------
__global__ void hist_kernel(const int* __restrict__ dst,
                            int* __restrict__ count, int n_edges)
{
    int i = blockIdx.x * blockDim.x + threadIdx.x;
    if (i < n_edges) atomicAdd(&count[dst[i]], 1);
}

// Block scan of counts + atomic base allocation (buckets contiguous,
// block-order arbitrary — aggregate only needs [start, start+count)).
__global__ __launch_bounds__(1024) void scanalloc_kernel(
    const int* __restrict__ count, int* __restrict__ start,
    int* __restrict__ cursor, int* __restrict__ total, int n)
{
    __shared__ int warp_sums[32];
    __shared__ int block_base;

    const int tid  = threadIdx.x;
    const int lane = tid & 31;
    const int wid  = tid >> 5;
    const int gid  = blockIdx.x * 1024 + tid;

    int v = (gid < n) ? count[gid] : 0;

    int x = v;
#pragma unroll
    for (int off = 1; off < 32; off <<= 1) {
        int t = __shfl_up_sync(0xffffffffu, x, off);
        if (lane >= off) x += t;
    }
    if (lane == 31) warp_sums[wid] = x;
    __syncthreads();

    if (wid == 0) {
        int s = warp_sums[lane];
#pragma unroll
        for (int off = 1; off < 32; off <<= 1) {
            int t = __shfl_up_sync(0xffffffffu, s, off);
            if (lane >= off) s += t;
        }
        warp_sums[lane] = s;
        if (lane == 31) block_base = atomicAdd(total, s);
    }
    __syncthreads();

    int prefix = block_base + (wid > 0 ? warp_sums[wid - 1] : 0) + (x - v);
    if (gid < n) {
        start[gid]  = prefix;
        cursor[gid] = prefix;
    }
}

__global__ void scatter_kernel(const int* __restrict__ src,
                               const int* __restrict__ dst,
                               const float* __restrict__ ew,
                               int* __restrict__ cursor,
                               int2* __restrict__ edge, int n_edges)
{
    int i = blockIdx.x * blockDim.x + threadIdx.x;
    if (i >= n_edges) return;
    int d = dst[i];
    int pos = atomicAdd(&cursor[d], 1);
    edge[pos] = make_int2(src[i], __float_as_int(ew[i]));
}

// ---------------------------------------------------------------------------
// Aggregate: one warp per node; lane owns 2 feats. Edge chunks are
// software-pipelined (prefetch next chunk before the shfl/FMA loop).
// out[n] = relu(sum_{e in bucket(n)} h[src_e] * w_e + bias)
// ---------------------------------------------------------------------------
__global__ __launch_bounds__(256) void aggregate_kernel(
    const float* __restrict__ h,
    const int* __restrict__ start,
    const int* __restrict__ count,
    const int2* __restrict__ edge,
    const float* __restrict__ bias,
    float* __restrict__ out, int n_nodes)
{
    const int lane = threadIdx.x & 31;
    const int node = (blockIdx.x * blockDim.x + threadIdx.x) >> 5;
    if (node >= n_nodes) return;

    const int beg = start[node];
    const int end = beg + count[node];

    float2 acc = make_float2(0.f, 0.f);

    int idx = beg + lane;
    int2 e = (idx < end) ? edge[idx] : make_int2(0, 0);   // w=0.0f pad

    for (int j = beg; j < end; j += 32) {
        int2 cur = e;
        int cnt  = min(32, end - j);
        // prefetch next chunk
        int nidx = j + 32 + lane;
        if (j + 32 < end)
            e = (nidx < end) ? edge[nidx] : make_int2(0, 0);

#pragma unroll 8
        for (int i = 0; i < cnt; i++) {
            int   si = __shfl_sync(0xffffffffu, cur.x, i);
            float wi = __int_as_float(__shfl_sync(0xffffffffu, cur.y, i));
            float2 hv = *(const float2*)&h[(size_t)si * OUT_FEATS + lane * 2];
            acc.x = fmaf(hv.x, wi, acc.x);
            acc.y = fmaf(hv.y, wi, acc.y);
        }
    }

    float2 bv = *(const float2*)&bias[lane * 2];
    acc.x = fmaxf(acc.x + bv.x, 0.f);
    acc.y = fmaxf(acc.y + bv.y, 0.f);
    *(float2*)&out[(size_t)node * OUT_FEATS + lane * 2] = acc;
}

// ---------------------------------------------------------------------------
// Launch
// ---------------------------------------------------------------------------
extern "C" void kernel_launch(void* const* d_in, const int* in_sizes, int n_in,
                              void* d_out, int out_size)
{
    const float* x    = (const float*)d_in[0];
    const int*   src  = (const int*)d_in[1];
    const int*   dst  = (const int*)d_in[2];
    const float* ew   = (const float*)d_in[3];
    const float* w    = (const float*)d_in[4];
    const float* bias = (const float*)d_in[5];
    float*       out  = (float*)d_out;

    const int n_nodes = in_sizes[0] / IN_FEATS;
    const int n_edges = in_sizes[1];

    float* h;      cudaGetSymbolAddress((void**)&h,      g_h);
    int*   count;  cudaGetSymbolAddress((void**)&count,  g_count);
    int*   start;  cudaGetSymbolAddress((void**)&start,  g_start);
    int*   cursor; cudaGetSymbolAddress((void**)&cursor, g_cursor);
    int*   total;  cudaGetSymbolAddress((void**)&total,  g_total);
    int2*  edge;   cudaGetSymbolAddress((void**)&edge,   g_edge);

    // 1) h = x @ W  (bf16 split tensor-core GEMM) + zero CSR counters
    gemm_bf16x_kernel<<<(n_nodes + BM - 1) / BM, 256>>>(x, w, h, n_nodes,
                                                        count, total, n_nodes);

    // 2) reverse-CSR build
    hist_kernel<<<(n_edges + 255) / 256, 256>>>(dst, count, n_edges);
    scanalloc_kernel<<<(n_nodes + 1023) / 1024, 1024>>>(count, start, cursor,
                                                        total, n_nodes);
    scatter_kernel<<<(n_edges + 255) / 256, 256>>>(src, dst, ew, cursor,
                                                   edge, n_edges);

    // 3) aggregate + bias + relu (one warp per node, no float atomics)
    {
        long long threads = (long long)n_nodes * 32;
        int blocks = (int)((threads + 255) / 256);
        aggregate_kernel<<<blocks, 256>>>(h, start, count, edge, bias,
                                          out, n_nodes);
    }
}

// round 7
// speedup vs baseline: 1.4708x; 1.0294x over previous
#include <cuda_runtime.h>
#include <cuda_fp16.h>
#include <cstdint>

#define N_NODES_MAX 100032
#define E_MAX       1600000
#define IN_FEATS    256
#define OUT_FEATS   64
#define H_PITCH     32          // 32 x half2 per node row (64 fp16 feats)

// Scratch (all __device__ globals, no allocation):
__device__ unsigned g_h16[(size_t)N_NODES_MAX * H_PITCH];  // h in half2 pairs
__device__ int      g_count[N_NODES_MAX];
__device__ int      g_start[N_NODES_MAX];
__device__ int      g_cursor[N_NODES_MAX];
__device__ int      g_total;
__device__ int2     g_edge[E_MAX];                         // {src, w_bits}

// ---------------------------------------------------------------------------
// bf16 helpers: pack two floats to bf16x2 (x -> low, y -> high)
// ---------------------------------------------------------------------------
__device__ __forceinline__ unsigned pack_bf16x2(float lo, float hi) {
    unsigned r;
    asm("cvt.rn.bf16x2.f32 %0, %1, %2;" : "=r"(r) : "f"(hi), "f"(lo));
    return r;
}

__device__ __forceinline__ void split_bf16(float2 v, unsigned& hi, unsigned& lo) {
    hi = pack_bf16x2(v.x, v.y);
    float rx = v.x - __uint_as_float(hi << 16);
    float ry = v.y - __uint_as_float(hi & 0xffff0000u);
    lo = pack_bf16x2(rx, ry);
}

#define MMA_BF16(d, a, b)                                                     \
    asm volatile(                                                             \
        "mma.sync.aligned.m16n8k16.row.col.f32.bf16.bf16.f32 "                \
        "{%0,%1,%2,%3}, {%4,%5,%6,%7}, {%8,%9}, {%0,%1,%2,%3};"               \
        : "+f"(d[0]), "+f"(d[1]), "+f"(d[2]), "+f"(d[3])                      \
        : "r"(a[0]), "r"(a[1]), "r"(a[2]), "r"(a[3]), "r"(b[0]), "r"(b[1]))

// ---------------------------------------------------------------------------
// Zero CSR counters (must globally precede the fused hist in the GEMM).
// ---------------------------------------------------------------------------
__global__ void zero_kernel(int* __restrict__ count,
                            int* __restrict__ total, int n)
{
    int i = blockIdx.x * blockDim.x + threadIdx.x;
    if (i < n) count[i] = 0;
    if (i == 0) *total = 0;
}

// ---------------------------------------------------------------------------
// GEMM: h16[n,64] = fp16(x[n,256] @ W[256,64]) via 3-term bf16 split MMA.
// Block: 128M x 64N, 256 threads = 8 warps (4x2), warp tile 32x32.
// Tail: fused dst-histogram (overlaps with other blocks' tensor work).
// ---------------------------------------------------------------------------
#define BM 128
#define BK 32
#define XS_PITCH 40
#define WS_PITCH 68

__global__ __launch_bounds__(256) void gemm_bf16x_kernel(
    const float* __restrict__ x, const float* __restrict__ w,
    unsigned* __restrict__ h16, int n_rows,
    const int* __restrict__ dst, int* __restrict__ count, int n_edges)
{
    __shared__ float xs[BM][XS_PITCH];
    __shared__ float ws[BK][WS_PITCH];

    const int tid    = threadIdx.x;
    const int lane   = tid & 31;
    const int wid    = tid >> 5;
    const int warp_m = wid >> 1;
    const int warp_n = wid & 1;
    const int lq     = lane >> 2;
    const int lr     = lane & 3;
    const int row0   = blockIdx.x * BM;

    float acc[2][4][4];
#pragma unroll
    for (int mt = 0; mt < 2; mt++)
#pragma unroll
        for (int nt = 0; nt < 4; nt++)
#pragma unroll
            for (int r = 0; r < 4; r++) acc[mt][nt][r] = 0.f;

    for (int kk = 0; kk < IN_FEATS; kk += BK) {
#pragma unroll
        for (int it = 0; it < 4; it++) {
            int idx = it * 256 + tid;
            int r   = idx >> 3;
            int kq  = idx & 7;
            float4 v = make_float4(0.f, 0.f, 0.f, 0.f);
            int row = row0 + r;
            if (row < n_rows)
                v = *(const float4*)&x[(size_t)row * IN_FEATS + kk + kq * 4];
            *(float4*)&xs[r][kq * 4] = v;
        }
#pragma unroll
        for (int it = 0; it < 2; it++) {
            int idx = it * 256 + tid;
            int kr  = idx >> 4;
            int c4  = idx & 15;
            *(float4*)&ws[kr][c4 * 4] =
                *(const float4*)&w[(size_t)(kk + kr) * OUT_FEATS + c4 * 4];
        }
        __syncthreads();

#pragma unroll
        for (int ks = 0; ks < 2; ks++) {
            const int kb = ks * 16;

            unsigned ahi[2][4], alo[2][4];
#pragma unroll
            for (int mt = 0; mt < 2; mt++) {
                int mrow = warp_m * 32 + mt * 16;
                float2 a0 = *(const float2*)&xs[mrow + lq    ][kb + 2 * lr    ];
                float2 a1 = *(const float2*)&xs[mrow + lq + 8][kb + 2 * lr    ];
                float2 a2 = *(const float2*)&xs[mrow + lq    ][kb + 2 * lr + 8];
                float2 a3 = *(const float2*)&xs[mrow + lq + 8][kb + 2 * lr + 8];
                split_bf16(a0, ahi[mt][0], alo[mt][0]);
                split_bf16(a1, ahi[mt][1], alo[mt][1]);
                split_bf16(a2, ahi[mt][2], alo[mt][2]);
                split_bf16(a3, ahi[mt][3], alo[mt][3]);
            }
            unsigned bhi[4][2], blo[4][2];
#pragma unroll
            for (int nt = 0; nt < 4; nt++) {
                int ncol = warp_n * 32 + nt * 8 + lq;
                float2 b0 = make_float2(ws[kb + 2 * lr    ][ncol],
                                        ws[kb + 2 * lr + 1][ncol]);
                float2 b1 = make_float2(ws[kb + 2 * lr + 8][ncol],
                                        ws[kb + 2 * lr + 9][ncol]);
                split_bf16(b0, bhi[nt][0], blo[nt][0]);
                split_bf16(b1, bhi[nt][1], blo[nt][1]);
            }

#pragma unroll
            for (int mt = 0; mt < 2; mt++)
#pragma unroll
                for (int nt = 0; nt < 4; nt++) {
                    MMA_BF16(acc[mt][nt], ahi[mt], bhi[nt]);
                    MMA_BF16(acc[mt][nt], ahi[mt], blo[nt]);
                    MMA_BF16(acc[mt][nt], alo[mt], bhi[nt]);
                }
        }
        __syncthreads();
    }

    // epilogue: pack col pairs to half2; pair index = warp_n*16 + nt*4 + lr
#pragma unroll
    for (int mt = 0; mt < 2; mt++) {
        int rbase = row0 + warp_m * 32 + mt * 16 + lq;
#pragma unroll
        for (int nt = 0; nt < 4; nt++) {
            int cp = warp_n * 16 + nt * 4 + lr;
            if (rbase < n_rows) {
                __half2 p = __floats2half2_rn(acc[mt][nt][0], acc[mt][nt][1]);
                h16[(size_t)rbase * H_PITCH + cp] = *(unsigned*)&p;
            }
            if (rbase + 8 < n_rows) {
                __half2 p = __floats2half2_rn(acc[mt][nt][2], acc[mt][nt][3]);
                h16[(size_t)(rbase + 8) * H_PITCH + cp] = *(unsigned*)&p;
            }
        }
    }

    // fused dst histogram (counters pre-zeroed by zero_kernel)
    const int stride = gridDim.x * 256;
    for (int e = blockIdx.x * 256 + tid; e < n_edges; e += stride)
        atomicAdd(&count[dst[e]], 1);
}

// ---------------------------------------------------------------------------
// Block scan of counts + atomic base allocation (buckets contiguous,
// block-order arbitrary).
// ---------------------------------------------------------------------------
__global__ __launch_bounds__(1024) void scanalloc_kernel(
    const int* __restrict__ count, int* __restrict__ start,
    int* __restrict__ cursor, int* __restrict__ total, int n)
{
    __shared__ int warp_sums[32];
    __shared__ int block_base;

    const int tid  = threadIdx.x;
    const int lane = tid & 31;
    const int wid  = tid >> 5;
    const int gid  = blockIdx.x * 1024 + tid;

    int v = (gid < n) ? count[gid] : 0;

    int x = v;
#pragma unroll
    for (int off = 1; off < 32; off <<= 1) {
        int t = __shfl_up_sync(0xffffffffu, x, off);
        if (lane >= off) x += t;
    }
    if (lane == 31) warp_sums[wid] = x;
    __syncthreads();

    if (wid == 0) {
        int s = warp_sums[lane];
#pragma unroll
        for (int off = 1; off < 32; off <<= 1) {
            int t = __shfl_up_sync(0xffffffffu, s, off);
            if (lane >= off) s += t;
        }
        warp_sums[lane] = s;
        if (lane == 31) block_base = atomicAdd(total, s);
    }
    __syncthreads();

    int prefix = block_base + (wid > 0 ? warp_sums[wid - 1] : 0) + (x - v);
    if (gid < n) {
        start[gid]  = prefix;
        cursor[gid] = prefix;
    }
}

// ---------------------------------------------------------------------------
// Scatter: 4 edges per thread (vectorized loads, 4 independent atomic chains).
// ---------------------------------------------------------------------------
__global__ __launch_bounds__(256) void scatter_kernel(
    const int* __restrict__ src,
    const int* __restrict__ dst,
    const float* __restrict__ ew,
    int* __restrict__ cursor,
    int2* __restrict__ edge, int n_edges)
{
    int base = (blockIdx.x * blockDim.x + threadIdx.x) * 4;
    if (base + 3 < n_edges) {
        int4   s4 = *(const int4*)&src[base];
        int4   d4 = *(const int4*)&dst[base];
        float4 w4 = *(const float4*)&ew[base];
        int p0 = atomicAdd(&cursor[d4.x], 1);
        int p1 = atomicAdd(&cursor[d4.y], 1);
        int p2 = atomicAdd(&cursor[d4.z], 1);
        int p3 = atomicAdd(&cursor[d4.w], 1);
        edge[p0] = make_int2(s4.x, __float_as_int(w4.x));
        edge[p1] = make_int2(s4.y, __float_as_int(w4.y));
        edge[p2] = make_int2(s4.z, __float_as_int(w4.z));
        edge[p3] = make_int2(s4.w, __float_as_int(w4.w));
    } else {
        for (int i = base; i < n_edges; i++) {
            int pos = atomicAdd(&cursor[dst[i]], 1);
            edge[pos] = make_int2(src[i], __float_as_int(ew[i]));
        }
    }
}

// ---------------------------------------------------------------------------
// Aggregate: one warp per node; lane owns 2 feats (one half2 of h).
// out[n] = relu(sum_{e in bucket(n)} h16[src_e] * w_e + bias)
// ---------------------------------------------------------------------------
__global__ __launch_bounds__(256) void aggregate_kernel(
    const unsigned* __restrict__ h16,
    const int* __restrict__ start,
    const int* __restrict__ count,
    const int2* __restrict__ edge,
    const float* __restrict__ bias,
    float* __restrict__ out, int n_nodes)
{
    const int lane = threadIdx.x & 31;
    const int node = (blockIdx.x * blockDim.x + threadIdx.x) >> 5;
    if (node >= n_nodes) return;

    const int beg = start[node];
    const int end = beg + count[node];

    float2 acc = make_float2(0.f, 0.f);

    int idx = beg + lane;
    int2 e = (idx < end) ? edge[idx] : make_int2(0, 0);   // w=0.0f pad

    for (int j = beg; j < end; j += 32) {
        int2 cur = e;
        int cnt  = min(32, end - j);
        // prefetch next edge chunk
        int nidx = j + 32 + lane;
        if (j + 32 < end)
            e = (nidx < end) ? edge[nidx] : make_int2(0, 0);

#pragma unroll 8
        for (int i = 0; i < cnt; i++) {
            int   si = __shfl_sync(0xffffffffu, cur.x, i);
            float wi = __int_as_float(__shfl_sync(0xffffffffu, cur.y, i));
            unsigned hu = h16[(size_t)si * H_PITCH + lane];
            float2 hv = __half22float2(*(__half2*)&hu);
            acc.x = fmaf(hv.x, wi, acc.x);
            acc.y = fmaf(hv.y, wi, acc.y);
        }
    }

    float2 bv = *(const float2*)&bias[lane * 2];
    acc.x = fmaxf(acc.x + bv.x, 0.f);
    acc.y = fmaxf(acc.y + bv.y, 0.f);
    *(float2*)&out[(size_t)node * OUT_FEATS + lane * 2] = acc;
}

// ---------------------------------------------------------------------------
// Launch
// ---------------------------------------------------------------------------
extern "C" void kernel_launch(void* const* d_in, const int* in_sizes, int n_in,
                              void* d_out, int out_size)
{
    const float* x    = (const float*)d_in[0];
    const int*   src  = (const int*)d_in[1];
    const int*   dst  = (const int*)d_in[2];
    const float* ew   = (const float*)d_in[3];
    const float* w    = (const float*)d_in[4];
    const float* bias = (const float*)d_in[5];
    float*       out  = (float*)d_out;

    const int n_nodes = in_sizes[0] / IN_FEATS;
    const int n_edges = in_sizes[1];

    unsigned* h16;   cudaGetSymbolAddress((void**)&h16,    g_h16);
    int*      count; cudaGetSymbolAddress((void**)&count,  g_count);
    int*      start; cudaGetSymbolAddress((void**)&start,  g_start);
    int*      cursor;cudaGetSymbolAddress((void**)&cursor, g_cursor);
    int*      total; cudaGetSymbolAddress((void**)&total,  g_total);
    int2*     edge;  cudaGetSymbolAddress((void**)&edge,   g_edge);

    // 1) zero CSR counters (must precede fused hist)
    zero_kernel<<<(n_nodes + 255) / 256, 256>>>(count, total, n_nodes);

    // 2) h16 = fp16(x @ W) + fused dst histogram
    gemm_bf16x_kernel<<<(n_nodes + BM - 1) / BM, 256>>>(x, w, h16, n_nodes,
                                                        dst, count, n_edges);

    // 3) scan + bucket allocation
    scanalloc_kernel<<<(n_nodes + 1023) / 1024, 1024>>>(count, start, cursor,
                                                        total, n_nodes);

    // 4) scatter edges into buckets (4 edges / thread)
    scatter_kernel<<<(n_edges / 4 + 255) / 256, 256>>>(src, dst, ew, cursor,
                                                       edge, n_edges);

    // 5) aggregate + bias + relu
    {
        long long threads = (long long)n_nodes * 32;
        int blocks = (int)((threads + 255) / 256);
        aggregate_kernel<<<blocks, 256>>>(h16, start, count, edge, bias,
                                          out, n_nodes);
    }
}